// round 2
// baseline (speedup 1.0000x reference)
#include <cuda_runtime.h>
#include <math.h>

#define NN   50000
#define EE   1600000
#define ETOT (EE + NN)
#define DHF  128

// -------- scratch (static __device__ globals; allocation-free kernel_launch) --------
__device__ float g_h[(size_t)NN * DHF];   // transformed features h = x @ W
__device__ float g_x[(size_t)NN * DHF];   // layer outputs x1 / x2
__device__ float g_s[NN];                 // h . att_src
__device__ float g_d[NN];                 // h . att_dst
__device__ int   g_cnt[NN];
__device__ int   g_rowptr[NN + 1];
__device__ int   g_fill[NN];
__device__ int   g_srcs[ETOT];            // src node id per edge, sorted by dst (CSR)

// ---------------- CSR build ----------------
__global__ void k_zero_cnt() {
    int i = blockIdx.x * blockDim.x + threadIdx.x;
    if (i < NN) g_cnt[i] = 0;
}

__global__ void k_hist(const int* __restrict__ ei) {
    int i = blockIdx.x * blockDim.x + threadIdx.x;
    if (i >= ETOT) return;
    int dst = (i < EE) ? ei[EE + i] : (i - EE);
    atomicAdd(&g_cnt[dst], 1);
}

// single-block chunked exclusive scan over g_cnt -> g_rowptr, g_fill
__global__ void k_scan() {
    __shared__ int warp_tot[32];
    __shared__ int carry_sh;
    int t = threadIdx.x;
    int lane = t & 31, w = t >> 5;
    if (t == 0) carry_sh = 0;
    __syncthreads();
    for (int base = 0; base < NN; base += 1024) {
        int idx = base + t;
        int v = (idx < NN) ? g_cnt[idx] : 0;
        int x = v;
        #pragma unroll
        for (int o = 1; o < 32; o <<= 1) {
            int y = __shfl_up_sync(0xffffffffu, x, o);
            if (lane >= o) x += y;
        }
        if (lane == 31) warp_tot[w] = x;
        __syncthreads();
        if (w == 0) {
            int y = warp_tot[lane];
            #pragma unroll
            for (int o = 1; o < 32; o <<= 1) {
                int z = __shfl_up_sync(0xffffffffu, y, o);
                if (lane >= o) y += z;
            }
            warp_tot[lane] = y;
        }
        __syncthreads();
        int incl = x + ((w > 0) ? warp_tot[w - 1] : 0);
        int excl = carry_sh + incl - v;
        if (idx < NN) { g_rowptr[idx] = excl; g_fill[idx] = excl; }
        __syncthreads();
        if (t == 1023) carry_sh += incl;   // thread 1023's inclusive = chunk total
        __syncthreads();
    }
    if (t == 0) g_rowptr[NN] = carry_sh;
}

__global__ void k_scatter(const int* __restrict__ ei) {
    int i = blockIdx.x * blockDim.x + threadIdx.x;
    if (i >= ETOT) return;
    int src, dst;
    if (i < EE) { src = ei[i]; dst = ei[EE + i]; }
    else        { src = i - EE; dst = i - EE; }
    int pos = atomicAdd(&g_fill[dst], 1);
    g_srcs[pos] = src;
}

// ---------------- dense GEMM: C[M,NC] = A[M,128] @ W[128,NC] (+bias) ----------------
template <int NC, bool BIAS>
__global__ void k_gemm(const float* __restrict__ A, const float* __restrict__ W,
                       const float* __restrict__ bias, float* __restrict__ C, int M) {
    __shared__ float As[32][32];
    __shared__ float Ws[32][NC];
    constexpr int CG  = NC / 4;        // column groups of 4
    constexpr int RG  = 256 / CG;      // row groups
    constexpr int RPT = 32 / RG;       // rows per thread
    int t  = threadIdx.x;
    int cg = t % CG, rg = t / CG;
    int row0 = blockIdx.x * 32;

    float acc[RPT][4];
    #pragma unroll
    for (int rr = 0; rr < RPT; rr++)
        acc[rr][0] = acc[rr][1] = acc[rr][2] = acc[rr][3] = 0.f;

    for (int k0 = 0; k0 < 128; k0 += 32) {
        // A chunk: 32 rows x 32 k (256 float4 -> one per thread)
        {
            int r = t >> 3, c = t & 7;
            float4 v = make_float4(0.f, 0.f, 0.f, 0.f);
            if (row0 + r < M)
                v = *(const float4*)&A[(size_t)(row0 + r) * 128 + k0 + c * 4];
            *(float4*)&As[r][c * 4] = v;
        }
        // W chunk: 32 x NC
        for (int i = t; i < 32 * (NC / 4); i += 256) {
            int r = i / (NC / 4), c = i % (NC / 4);
            *(float4*)&Ws[r][c * 4] = *(const float4*)&W[(size_t)(k0 + r) * NC + c * 4];
        }
        __syncthreads();
        #pragma unroll
        for (int k = 0; k < 32; k++) {
            float4 wv = *(float4*)&Ws[k][cg * 4];
            #pragma unroll
            for (int rr = 0; rr < RPT; rr++) {
                float a = As[rg * RPT + rr][k];
                acc[rr][0] += a * wv.x;
                acc[rr][1] += a * wv.y;
                acc[rr][2] += a * wv.z;
                acc[rr][3] += a * wv.w;
            }
        }
        __syncthreads();
    }
    #pragma unroll
    for (int rr = 0; rr < RPT; rr++) {
        int r = row0 + rg * RPT + rr;
        if (r < M) {
            float4 v = make_float4(acc[rr][0], acc[rr][1], acc[rr][2], acc[rr][3]);
            if (BIAS) {
                v.x += bias[cg * 4 + 0];
                v.y += bias[cg * 4 + 1];
                v.z += bias[cg * 4 + 2];
                v.w += bias[cg * 4 + 3];
            }
            *(float4*)&C[(size_t)r * NC + cg * 4] = v;
        }
    }
}

// ---------------- per-node attention scalars s = h.att_src, d = h.att_dst ----------------
__global__ void k_sd(const float* __restrict__ h,
                     const float* __restrict__ att_s, const float* __restrict__ att_d) {
    int gw   = (blockIdx.x * blockDim.x + threadIdx.x) >> 5;
    int lane = threadIdx.x & 31;
    if (gw >= NN) return;
    float4 hv = *(const float4*)&h[(size_t)gw * 128 + lane * 4];
    float4 av = *(const float4*)&att_s[lane * 4];
    float4 dv = *(const float4*)&att_d[lane * 4];
    float ps = hv.x * av.x + hv.y * av.y + hv.z * av.z + hv.w * av.w;
    float pd = hv.x * dv.x + hv.y * dv.y + hv.z * dv.z + hv.w * dv.w;
    #pragma unroll
    for (int o = 16; o; o >>= 1) {
        ps += __shfl_xor_sync(0xffffffffu, ps, o);
        pd += __shfl_xor_sync(0xffffffffu, pd, o);
    }
    if (lane == 0) { g_s[gw] = ps; g_d[gw] = pd; }
}

// ---------------- GAT aggregation: one warp per destination node ----------------
template <bool RELU>
__global__ void k_agg(const float* __restrict__ h, const float* __restrict__ bias,
                      float* __restrict__ out) {
    int node = (blockIdx.x * blockDim.x + threadIdx.x) >> 5;
    int lane = threadIdx.x & 31;
    if (node >= NN) return;
    int beg = g_rowptr[node], end = g_rowptr[node + 1];
    float di = g_d[node];

    // pass 1a: segment max (LeakyReLU slope 0 == relu, so logits >= 0)
    float m = -1e30f;
    for (int j = beg + lane; j < end; j += 32) {
        float e = fmaxf(g_s[g_srcs[j]] + di, 0.f);
        m = fmaxf(m, e);
    }
    #pragma unroll
    for (int o = 16; o; o >>= 1) m = fmaxf(m, __shfl_xor_sync(0xffffffffu, m, o));

    // pass 1b: denominator
    float sum = 0.f;
    for (int j = beg + lane; j < end; j += 32) {
        float e = fmaxf(g_s[g_srcs[j]] + di, 0.f);
        sum += __expf(e - m);
    }
    #pragma unroll
    for (int o = 16; o; o >>= 1) sum += __shfl_xor_sync(0xffffffffu, sum, o);
    float inv = 1.0f / sum;   // >= 1 term always present (self loop)

    // pass 2: weighted feature gather; lane owns 4 contiguous columns
    float4 acc = make_float4(0.f, 0.f, 0.f, 0.f);
    for (int j = beg; j < end; j++) {
        int   sj = g_srcs[j];                       // uniform across warp
        float e  = fmaxf(g_s[sj] + di, 0.f);
        float wg = __expf(e - m) * inv;
        float4 hv = *(const float4*)&h[(size_t)sj * 128 + lane * 4];
        acc.x += wg * hv.x;
        acc.y += wg * hv.y;
        acc.z += wg * hv.z;
        acc.w += wg * hv.w;
    }
    float4 bv = *(const float4*)&bias[lane * 4];
    acc.x += bv.x; acc.y += bv.y; acc.z += bv.z; acc.w += bv.w;
    if (RELU) {
        acc.x = fmaxf(acc.x, 0.f); acc.y = fmaxf(acc.y, 0.f);
        acc.z = fmaxf(acc.z, 0.f); acc.w = fmaxf(acc.w, 0.f);
    }
    *(float4*)&out[(size_t)node * 128 + lane * 4] = acc;
}

// ---------------- launcher ----------------
extern "C" void kernel_launch(void* const* d_in, const int* in_sizes, int n_in,
                              void* d_out, int out_size) {
    const float* node_x   = (const float*)d_in[0];
    const int*   edge_idx = (const int*)  d_in[1];
    const float* W1       = (const float*)d_in[2];
    const float* as1      = (const float*)d_in[3];
    const float* ad1      = (const float*)d_in[4];
    const float* b1       = (const float*)d_in[5];
    const float* W2       = (const float*)d_in[6];
    const float* as2      = (const float*)d_in[7];
    const float* ad2      = (const float*)d_in[8];
    const float* b2       = (const float*)d_in[9];
    const float* W_out    = (const float*)d_in[10];
    const float* b_out    = (const float*)d_in[11];
    float*       out      = (float*)d_out;

    float *d_h, *d_x;
    cudaGetSymbolAddress((void**)&d_h, g_h);
    cudaGetSymbolAddress((void**)&d_x, g_x);

    const int T = 256;
    int g_nodes = (NN + T - 1) / T;
    int g_edges = (ETOT + T - 1) / T;
    int g_warpN = (NN * 32 + T - 1) / T;
    int g_gemm  = (NN + 31) / 32;

    // CSR build (edges identical for both layers)
    k_zero_cnt<<<g_nodes, T>>>();
    k_hist<<<g_edges, T>>>(edge_idx);
    k_scan<<<1, 1024>>>();
    k_scatter<<<g_edges, T>>>(edge_idx);

    // layer 1
    k_gemm<128, false><<<g_gemm, T>>>(node_x, W1, nullptr, d_h, NN);
    k_sd<<<g_warpN, T>>>(d_h, as1, ad1);
    k_agg<true><<<g_warpN, T>>>(d_h, b1, d_x);

    // layer 2
    k_gemm<128, false><<<g_gemm, T>>>(d_x, W2, nullptr, d_h, NN);
    k_sd<<<g_warpN, T>>>(d_h, as2, ad2);
    k_agg<false><<<g_warpN, T>>>(d_h, b2, d_x);

    // output linear
    k_gemm<64, true><<<g_gemm, T>>>(d_x, W_out, b_out, out, NN);
}

// round 5
// speedup vs baseline: 1.0553x; 1.0553x over previous
#include <cuda_runtime.h>
#include <cuda_bf16.h>
#include <math.h>
#include <stdint.h>

#define NN   50000
#define EE   1600000
#define ETOT (EE + NN)
#define DHF  128

// -------- scratch --------
__device__ float g_h[(size_t)NN * DHF];
__device__ float g_x[(size_t)NN * DHF];
__device__ float g_s[NN];
__device__ float g_d[NN];
__device__ int   g_cnt[NN];
__device__ int   g_rowptr[NN + 1];
__device__ int   g_fill[NN];
__device__ int   g_srcs[ETOT];

// ================= CSR build =================
__global__ void k_zero_cnt() {
    int i = blockIdx.x * blockDim.x + threadIdx.x;
    if (i < NN) g_cnt[i] = 0;
}
__global__ void k_hist(const int* __restrict__ ei) {
    int i = blockIdx.x * blockDim.x + threadIdx.x;
    if (i >= ETOT) return;
    int dst = (i < EE) ? ei[EE + i] : (i - EE);
    atomicAdd(&g_cnt[dst], 1);
}
__global__ void k_scan() {
    __shared__ int warp_tot[32];
    __shared__ int carry_sh;
    int t = threadIdx.x, lane = t & 31, w = t >> 5;
    if (t == 0) carry_sh = 0;
    __syncthreads();
    for (int base = 0; base < NN; base += 1024) {
        int idx = base + t;
        int v = (idx < NN) ? g_cnt[idx] : 0;
        int x = v;
        #pragma unroll
        for (int o = 1; o < 32; o <<= 1) {
            int y = __shfl_up_sync(0xffffffffu, x, o);
            if (lane >= o) x += y;
        }
        if (lane == 31) warp_tot[w] = x;
        __syncthreads();
        if (w == 0) {
            int y = warp_tot[lane];
            #pragma unroll
            for (int o = 1; o < 32; o <<= 1) {
                int z = __shfl_up_sync(0xffffffffu, y, o);
                if (lane >= o) y += z;
            }
            warp_tot[lane] = y;
        }
        __syncthreads();
        int incl = x + ((w > 0) ? warp_tot[w - 1] : 0);
        int excl = carry_sh + incl - v;
        if (idx < NN) { g_rowptr[idx] = excl; g_fill[idx] = excl; }
        __syncthreads();
        if (t == 1023) carry_sh += incl;
        __syncthreads();
    }
    if (t == 0) g_rowptr[NN] = carry_sh;
}
__global__ void k_scatter(const int* __restrict__ ei) {
    int i = blockIdx.x * blockDim.x + threadIdx.x;
    if (i >= ETOT) return;
    int src, dst;
    if (i < EE) { src = ei[i]; dst = ei[EE + i]; }
    else        { src = i - EE; dst = i - EE; }
    int pos = atomicAdd(&g_fill[dst], 1);
    g_srcs[pos] = src;
}

// ================= HMMA GEMM: C[M,NB] = A[M,128] @ W[128,NB] =================
// bf16 3-term split (AhiBhi + AhiBlo + AloBhi), fp32 accum -> rel_err ~1e-5.
// One block = 128 rows; 8 warps x (16 rows x NB cols) via mma.sync.m16n8k16.
// SD: fused per-row dots s = C.att_src, d = C.att_dst in the epilogue.
__device__ __forceinline__ void mma16816(float* c, uint32_t a0, uint32_t a1,
                                         uint32_t a2, uint32_t a3,
                                         uint32_t b0, uint32_t b1) {
    asm volatile(
        "mma.sync.aligned.m16n8k16.row.col.f32.bf16.bf16.f32 "
        "{%0,%1,%2,%3}, {%4,%5,%6,%7}, {%8,%9}, {%0,%1,%2,%3};"
        : "+f"(c[0]), "+f"(c[1]), "+f"(c[2]), "+f"(c[3])
        : "r"(a0), "r"(a1), "r"(a2), "r"(a3), "r"(b0), "r"(b1));
}

template <int NB, bool SD, bool BIAS>
__global__ void __launch_bounds__(256, 1)
k_mma(const float* __restrict__ A, const float* __restrict__ Wf,
      const float* __restrict__ atts, const float* __restrict__ attd,
      const float* __restrict__ bias, float* __restrict__ C, int M)
{
    constexpr int AS = 136;                 // padded bf16 row stride (bank = 4g+t, conflict-free)
    extern __shared__ __nv_bfloat16 sm[];
    __nv_bfloat16* sAhi = sm;               // [128][AS]
    __nv_bfloat16* sAlo = sAhi + 128 * AS;
    __nv_bfloat16* sBhi = sAlo + 128 * AS;  // Wt[n][k]: [NB][AS]
    __nv_bfloat16* sBlo = sBhi + NB * AS;

    int tid = threadIdx.x, wid = tid >> 5, lane = tid & 31;
    int g = lane >> 2, t4 = lane & 3;
    int row0 = blockIdx.x * 128;

    // A tile -> bf16 hi/lo
    for (int idx = tid; idx < 128 * 32; idx += 256) {
        int r = idx >> 5, c4 = (idx & 31) * 4;
        float4 v = make_float4(0.f, 0.f, 0.f, 0.f);
        if (row0 + r < M) v = *(const float4*)&A[(size_t)(row0 + r) * 128 + c4];
        float va[4] = {v.x, v.y, v.z, v.w};
        __nv_bfloat16 hi[4], lo[4];
        #pragma unroll
        for (int i = 0; i < 4; i++) {
            hi[i] = __float2bfloat16(va[i]);
            lo[i] = __float2bfloat16(va[i] - __bfloat162float(hi[i]));
        }
        int o = r * AS + c4;
        *(__nv_bfloat162*)&sAhi[o]     = __nv_bfloat162(hi[0], hi[1]);
        *(__nv_bfloat162*)&sAhi[o + 2] = __nv_bfloat162(hi[2], hi[3]);
        *(__nv_bfloat162*)&sAlo[o]     = __nv_bfloat162(lo[0], lo[1]);
        *(__nv_bfloat162*)&sAlo[o + 2] = __nv_bfloat162(lo[2], lo[3]);
    }
    // W[128,NB] row-major -> Wt[n][k] bf16 hi/lo
    for (int idx = tid; idx < 128 * NB; idx += 256) {
        int k = idx / NB, n = idx % NB;
        float w = Wf[idx];
        __nv_bfloat16 hi = __float2bfloat16(w);
        __nv_bfloat16 lo = __float2bfloat16(w - __bfloat162float(hi));
        sBhi[n * AS + k] = hi;
        sBlo[n * AS + k] = lo;
    }
    __syncthreads();

    float acc[NB / 8][4];
    #pragma unroll
    for (int nb = 0; nb < NB / 8; nb++)
        acc[nb][0] = acc[nb][1] = acc[nb][2] = acc[nb][3] = 0.f;

    int ar0 = (wid * 16 + g) * AS, ar1 = (wid * 16 + g + 8) * AS;
    #pragma unroll
    for (int pass = 0; pass < 3; pass++) {
        const __nv_bfloat16* Asrc = (pass == 2) ? sAlo : sAhi;
        const __nv_bfloat16* Bsrc = (pass == 1) ? sBlo : sBhi;
        #pragma unroll
        for (int k0 = 0; k0 < 8; k0++) {
            int kb = k0 * 16 + 2 * t4;
            uint32_t a0 = *(const uint32_t*)&Asrc[ar0 + kb];
            uint32_t a1 = *(const uint32_t*)&Asrc[ar1 + kb];
            uint32_t a2 = *(const uint32_t*)&Asrc[ar0 + kb + 8];
            uint32_t a3 = *(const uint32_t*)&Asrc[ar1 + kb + 8];
            #pragma unroll
            for (int nb = 0; nb < NB / 8; nb++) {
                uint32_t b0 = *(const uint32_t*)&Bsrc[(nb * 8 + g) * AS + kb];
                uint32_t b1 = *(const uint32_t*)&Bsrc[(nb * 8 + g) * AS + kb + 8];
                mma16816(acc[nb], a0, a1, a2, a3, b0, b1);
            }
        }
    }

    // epilogue: store + fused attention dots
    int r0 = row0 + wid * 16 + g, r1 = r0 + 8;
    float s0 = 0.f, d0 = 0.f, s1 = 0.f, d1 = 0.f;
    #pragma unroll
    for (int nb = 0; nb < NB / 8; nb++) {
        int c0 = nb * 8 + 2 * t4;
        float v0 = acc[nb][0], v1 = acc[nb][1], v2 = acc[nb][2], v3 = acc[nb][3];
        if (BIAS) {
            float bb0 = bias[c0], bb1 = bias[c0 + 1];
            v0 += bb0; v1 += bb1; v2 += bb0; v3 += bb1;
        }
        if (r0 < M) *(float2*)&C[(size_t)r0 * NB + c0] = make_float2(v0, v1);
        if (r1 < M) *(float2*)&C[(size_t)r1 * NB + c0] = make_float2(v2, v3);
        if (SD) {
            float as0 = atts[c0], as1 = atts[c0 + 1];
            float ad0 = attd[c0], ad1 = attd[c0 + 1];
            s0 += v0 * as0 + v1 * as1;  d0 += v0 * ad0 + v1 * ad1;
            s1 += v2 * as0 + v3 * as1;  d1 += v2 * ad0 + v3 * ad1;
        }
    }
    if (SD) {
        #pragma unroll
        for (int o = 1; o < 4; o <<= 1) {
            s0 += __shfl_xor_sync(0xffffffffu, s0, o);
            d0 += __shfl_xor_sync(0xffffffffu, d0, o);
            s1 += __shfl_xor_sync(0xffffffffu, s1, o);
            d1 += __shfl_xor_sync(0xffffffffu, d1, o);
        }
        if (t4 == 0) {
            if (r0 < M) { g_s[r0] = s0; g_d[r0] = d0; }
            if (r1 < M) { g_s[r1] = s1; g_d[r1] = d1; }
        }
    }
}

// ================= GAT aggregation: one warp per dst node, single fused pass =================
// Logits are relu'd and O(1): exp never overflows; softmax is shift-invariant, so skip
// the max pass and normalize by the accumulated sum at the end.
template <bool RELU>
__global__ void k_agg(const float* __restrict__ h, const float* __restrict__ bias,
                      float* __restrict__ out) {
    int node = (blockIdx.x * blockDim.x + threadIdx.x) >> 5;
    int lane = threadIdx.x & 31;
    if (node >= NN) return;
    int beg = g_rowptr[node], end = g_rowptr[node + 1];
    float di = g_d[node];

    float4 acc = make_float4(0.f, 0.f, 0.f, 0.f);
    float sum = 0.f;
    int j = beg;
    for (; j + 1 < end; j += 2) {
        int s0 = g_srcs[j], s1 = g_srcs[j + 1];
        float w0 = __expf(fmaxf(g_s[s0] + di, 0.f));
        float w1 = __expf(fmaxf(g_s[s1] + di, 0.f));
        float4 h0 = *(const float4*)&h[(size_t)s0 * 128 + lane * 4];
        float4 h1 = *(const float4*)&h[(size_t)s1 * 128 + lane * 4];
        sum += w0 + w1;
        acc.x += w0 * h0.x + w1 * h1.x;
        acc.y += w0 * h0.y + w1 * h1.y;
        acc.z += w0 * h0.z + w1 * h1.z;
        acc.w += w0 * h0.w + w1 * h1.w;
    }
    if (j < end) {
        int s0 = g_srcs[j];
        float w0 = __expf(fmaxf(g_s[s0] + di, 0.f));
        float4 h0 = *(const float4*)&h[(size_t)s0 * 128 + lane * 4];
        sum += w0;
        acc.x += w0 * h0.x; acc.y += w0 * h0.y;
        acc.z += w0 * h0.z; acc.w += w0 * h0.w;
    }
    float inv = 1.0f / sum;   // self-loop guarantees sum >= 1
    float4 bv = *(const float4*)&bias[lane * 4];
    acc.x = acc.x * inv + bv.x; acc.y = acc.y * inv + bv.y;
    acc.z = acc.z * inv + bv.z; acc.w = acc.w * inv + bv.w;
    if (RELU) {
        acc.x = fmaxf(acc.x, 0.f); acc.y = fmaxf(acc.y, 0.f);
        acc.z = fmaxf(acc.z, 0.f); acc.w = fmaxf(acc.w, 0.f);
    }
    *(float4*)&out[(size_t)node * 128 + lane * 4] = acc;
}

// ================= launcher =================
extern "C" void kernel_launch(void* const* d_in, const int* in_sizes, int n_in,
                              void* d_out, int out_size) {
    const float* node_x   = (const float*)d_in[0];
    const int*   edge_idx = (const int*)  d_in[1];
    const float* W1       = (const float*)d_in[2];
    const float* as1      = (const float*)d_in[3];
    const float* ad1      = (const float*)d_in[4];
    const float* b1       = (const float*)d_in[5];
    const float* W2       = (const float*)d_in[6];
    const float* as2      = (const float*)d_in[7];
    const float* ad2      = (const float*)d_in[8];
    const float* b2       = (const float*)d_in[9];
    const float* W_out    = (const float*)d_in[10];
    const float* b_out    = (const float*)d_in[11];
    float*       out      = (float*)d_out;

    float *d_h, *d_x;
    cudaGetSymbolAddress((void**)&d_h, g_h);
    cudaGetSymbolAddress((void**)&d_x, g_x);

    const int T = 256;
    int grid_nodes = (NN + T - 1) / T;
    int grid_edges = (ETOT + T - 1) / T;
    int grid_warpN = (NN * 32 + T - 1) / T;
    int grid_mma   = (NN + 127) / 128;

    const int AS = 136;
    const int SM128 = (2 * 128 * AS + 2 * 128 * AS) * 2;  // ~139 KB
    const int SM64  = (2 * 128 * AS + 2 * 64 * AS) * 2;   // ~104 KB
    cudaFuncSetAttribute(k_mma<128, true, false>,
                         cudaFuncAttributeMaxDynamicSharedMemorySize, SM128);
    cudaFuncSetAttribute(k_mma<64, false, true>,
                         cudaFuncAttributeMaxDynamicSharedMemorySize, SM64);

    // CSR build
    k_zero_cnt<<<grid_nodes, T>>>();
    k_hist<<<grid_edges, T>>>(edge_idx);
    k_scan<<<1, 1024>>>();
    k_scatter<<<grid_edges, T>>>(edge_idx);

    // layer 1
    k_mma<128, true, false><<<grid_mma, T, SM128>>>(node_x, W1, as1, ad1, nullptr, d_h, NN);
    k_agg<true><<<grid_warpN, T>>>(d_h, b1, d_x);

    // layer 2
    k_mma<128, true, false><<<grid_mma, T, SM128>>>(d_x, W2, as2, ad2, nullptr, d_h, NN);
    k_agg<false><<<grid_warpN, T>>>(d_h, b2, d_x);

    // output linear
    k_mma<64, false, true><<<grid_mma, T, SM64>>>(d_x, W_out, nullptr, nullptr, b_out, out, NN);
}